// round 3
// baseline (speedup 1.0000x reference)
#include <cuda_runtime.h>
#include <cuda_bf16.h>
#include <cstdint>

#define N_MAX 100352          // padded to 512 multiple
#define E_MAX 1000000
#define HID 64

// ---------------- device scratch (no allocations allowed) ----------------
__device__ float g_H [100000 * HID];   // h / residual buffer
__device__ float g_HW[100000 * HID];   // h @ w buffer
__device__ float g_dinv[N_MAX];
__device__ int   g_hist[N_MAX];
__device__ int   g_offs[N_MAX];
__device__ int   g_cur [N_MAX];
__device__ int   g_part[256];
__device__ int   g_esrc[E_MAX];
__device__ int   g_is64;               // 1 if edge_index arrived as int64

// ---------------- edge dtype sniffer ----------------
// int64 node ids are < 100000 => high 32 bits always 0.
// int32 layout packs two ~uniform ids per u64 => nonzero high halves appear.
__global__ void k_detect(const unsigned long long* __restrict__ ei) {
    __shared__ int any;
    if (threadIdx.x == 0) any = 0;
    __syncthreads();
    for (int i = threadIdx.x; i < 1024; i += blockDim.x)
        if ((ei[i] >> 32) != 0ull) any = 1;
    __syncthreads();
    if (threadIdx.x == 0) g_is64 = (any == 0);
}

__device__ __forceinline__ int edge_at(const void* ei, int idx) {
    if (g_is64) return (int)((const long long*)ei)[idx];
    return ((const int*)ei)[idx];
}

// ---------------- degree / histogram ----------------
__global__ void k_zero_hist(int n) {
    int i = blockIdx.x * blockDim.x + threadIdx.x;
    if (i < n) g_hist[i] = 0;
}

__global__ void k_hist(const void* __restrict__ ei, int E) {
    int e = blockIdx.x * blockDim.x + threadIdx.x;
    if (e < E) {
        int d = edge_at(ei, E + e);        // dst row
        atomicAdd(&g_hist[d], 1);
    }
}

__global__ void k_dinv(int n) {
    int i = blockIdx.x * blockDim.x + threadIdx.x;
    if (i < n) g_dinv[i] = rsqrtf((float)g_hist[i] + 1.0f);   // +1 self loop
}

// ---------------- exclusive scan of hist (2-level) ----------------
__global__ void k_scan1(int n) {
    int idx = blockIdx.x * 512 + threadIdx.x;
    int v = (idx < n) ? g_hist[idx] : 0;
    int lane = threadIdx.x & 31, wid = threadIdx.x >> 5;
    int inc = v;
    #pragma unroll
    for (int o = 1; o < 32; o <<= 1) {
        int t = __shfl_up_sync(0xffffffffu, inc, o);
        if (lane >= o) inc += t;
    }
    __shared__ int wsum[16];
    if (lane == 31) wsum[wid] = inc;
    __syncthreads();
    if (wid == 0) {
        int s = (lane < 16) ? wsum[lane] : 0;
        #pragma unroll
        for (int o = 1; o < 16; o <<= 1) {
            int t = __shfl_up_sync(0xffffffffu, s, o);
            if (lane >= o) s += t;
        }
        if (lane < 16) wsum[lane] = s;
    }
    __syncthreads();
    int base = (wid > 0) ? wsum[wid - 1] : 0;
    if (idx < n) g_offs[idx] = base + inc - v;           // local exclusive
    if (threadIdx.x == 0) g_part[blockIdx.x] = wsum[15]; // block total
}

__global__ void k_scan2(int nb) {
    int t = threadIdx.x;                    // 256 threads, nb <= 256
    int v = (t < nb) ? g_part[t] : 0;
    int lane = t & 31, wid = t >> 5;
    int inc = v;
    #pragma unroll
    for (int o = 1; o < 32; o <<= 1) {
        int s = __shfl_up_sync(0xffffffffu, inc, o);
        if (lane >= o) inc += s;
    }
    __shared__ int wsum[8];
    if (lane == 31) wsum[wid] = inc;
    __syncthreads();
    if (wid == 0) {
        int s = (lane < 8) ? wsum[lane] : 0;
        #pragma unroll
        for (int o = 1; o < 8; o <<= 1) {
            int u = __shfl_up_sync(0xffffffffu, s, o);
            if (lane >= o) s += u;
        }
        if (lane < 8) wsum[lane] = s;
    }
    __syncthreads();
    int base = (wid > 0) ? wsum[wid - 1] : 0;
    if (t < nb) g_part[t] = base + inc - v; // exclusive
}

__global__ void k_scan3(int n) {
    int idx = blockIdx.x * 512 + threadIdx.x;
    if (idx < n) {
        int o = g_offs[idx] + g_part[blockIdx.x];
        g_offs[idx] = o;
        g_cur[idx]  = o;
    }
}

// ---------------- edge placement (counting sort by dst) ----------------
__global__ void k_place(const void* __restrict__ ei, int E) {
    int e = blockIdx.x * blockDim.x + threadIdx.x;
    if (e < E) {
        int s = edge_at(ei, e);
        int d = edge_at(ei, E + e);
        int pos = atomicAdd(&g_cur[d], 1);
        g_esrc[pos] = s;
    }
}

// ---------------- GEMM: C[n,64] = A[n,K] @ W[K,64] (+bias) ----------------
// 64x64 output tile per block, 256 threads, 4x4 per thread, K chunked by 64.
// A source: Aext if non-null, else g_H.  C dest: g_HW if dst_hw, else g_H.
__global__ void k_gemm(const float* __restrict__ Aext, const float* __restrict__ W,
                       const float* __restrict__ bias, int dst_hw,
                       int n, int K)
{
    const float* A = Aext ? Aext : (const float*)g_H;
    float* C = dst_hw ? g_HW : g_H;

    __shared__ float As[64][64];
    __shared__ float Ws[64][64];
    int row0 = blockIdx.x * 64;
    int tid = threadIdx.x;
    int tr = tid >> 4, tc = tid & 15;     // 16x16 thread grid
    float acc[4][4];
    #pragma unroll
    for (int r = 0; r < 4; r++)
        #pragma unroll
        for (int c = 0; c < 4; c++) acc[r][c] = 0.0f;

    for (int k0 = 0; k0 < K; k0 += 64) {
        #pragma unroll
        for (int i = tid; i < 64 * 16; i += 256) {
            int r = i >> 4, c4 = (i & 15) << 2;
            int gr = row0 + r;
            float4 v = (gr < n) ? *(const float4*)(A + (size_t)gr * K + k0 + c4)
                                : make_float4(0.f, 0.f, 0.f, 0.f);
            *(float4*)&As[r][c4] = v;
        }
        #pragma unroll
        for (int i = tid; i < 64 * 16; i += 256) {
            int r = i >> 4, c4 = (i & 15) << 2;
            *(float4*)&Ws[r][c4] = *(const float4*)(W + (size_t)(k0 + r) * 64 + c4);
        }
        __syncthreads();
        #pragma unroll
        for (int kk = 0; kk < 64; kk += 4) {
            float4 a[4], b[4];
            #pragma unroll
            for (int r = 0; r < 4; r++) a[r] = *(float4*)&As[tr * 4 + r][kk];
            #pragma unroll
            for (int j = 0; j < 4; j++) b[j] = *(float4*)&Ws[kk + j][tc * 4];
            #pragma unroll
            for (int j = 0; j < 4; j++) {
                #pragma unroll
                for (int r = 0; r < 4; r++) {
                    float av = (j == 0) ? a[r].x : (j == 1) ? a[r].y : (j == 2) ? a[r].z : a[r].w;
                    acc[r][0] = fmaf(av, b[j].x, acc[r][0]);
                    acc[r][1] = fmaf(av, b[j].y, acc[r][1]);
                    acc[r][2] = fmaf(av, b[j].z, acc[r][2]);
                    acc[r][3] = fmaf(av, b[j].w, acc[r][3]);
                }
            }
        }
        __syncthreads();
    }
    float4 bb = bias ? *(const float4*)(bias + tc * 4) : make_float4(0.f, 0.f, 0.f, 0.f);
    #pragma unroll
    for (int r = 0; r < 4; r++) {
        int gr = row0 + tr * 4 + r;
        if (gr < n) {
            float4 o = make_float4(acc[r][0] + bb.x, acc[r][1] + bb.y,
                                   acc[r][2] + bb.z, acc[r][3] + bb.w);
            *(float4*)(C + (size_t)gr * 64 + tc * 4) = o;
        }
    }
}

// ---------------- fused aggregate + bias + LayerNorm (+ReLU+residual) -----
// one warp per node; lane holds cols [2*lane, 2*lane+1]
// dst: out_ext if non-null, else g_H
__global__ void k_agg(const float* __restrict__ bias, const float* __restrict__ gma,
                      const float* __restrict__ beta, float* __restrict__ out_ext,
                      int n, int relu_res)
{
    int node = (blockIdx.x * blockDim.x + threadIdx.x) >> 5;
    if (node >= n) return;
    int lane = threadIdx.x & 31;
    float* out = out_ext ? out_ext : (float*)g_H;

    float di = g_dinv[node];
    const float2* hwrow = (const float2*)(g_HW + (size_t)node * HID);
    float2 acc = hwrow[lane];
    float self = di * di;
    acc.x *= self; acc.y *= self;

    int s0 = g_offs[node];
    int cnt = g_hist[node];
    for (int e = s0; e < s0 + cnt; e++) {
        int s = g_esrc[e];
        float nrm = g_dinv[s] * di;
        float2 v = ((const float2*)(g_HW + (size_t)s * HID))[lane];
        acc.x = fmaf(v.x, nrm, acc.x);
        acc.y = fmaf(v.y, nrm, acc.y);
    }
    float2 bb = ((const float2*)bias)[lane];
    acc.x += bb.x; acc.y += bb.y;

    // LayerNorm over 64 cols (2 per lane)
    float sum = acc.x + acc.y;
    #pragma unroll
    for (int o = 16; o; o >>= 1) sum += __shfl_xor_sync(0xffffffffu, sum, o);
    float mu = sum * (1.0f / 64.0f);
    float dx = acc.x - mu, dy = acc.y - mu;
    float vs = dx * dx + dy * dy;
    #pragma unroll
    for (int o = 16; o; o >>= 1) vs += __shfl_xor_sync(0xffffffffu, vs, o);
    float rstd = rsqrtf(vs * (1.0f / 64.0f) + 1e-5f);
    float2 gg = ((const float2*)gma)[lane];
    float2 be = ((const float2*)beta)[lane];
    float ox = dx * rstd * gg.x + be.x;
    float oy = dy * rstd * gg.y + be.y;

    if (relu_res) {
        float2 r = ((const float2*)(g_H + (size_t)node * HID))[lane];
        ox = fmaxf(ox, 0.0f) + r.x;
        oy = fmaxf(oy, 0.0f) + r.y;
    }
    ((float2*)(out + (size_t)node * HID))[lane] = make_float2(ox, oy);
}

// ---------------- launch ----------------
extern "C" void kernel_launch(void* const* d_in, const int* in_sizes, int n_in,
                              void* d_out, int out_size)
{
    const float* x      = (const float*)d_in[0];
    const void*  ei     = d_in[1];                 // int32 or int64, sniffed on device
    const float* proj_w = (const float*)d_in[2];
    const float* proj_b = (const float*)d_in[3];
    const float* w[3]  = { (const float*)d_in[4],  (const float*)d_in[8],  (const float*)d_in[12] };
    const float* b[3]  = { (const float*)d_in[5],  (const float*)d_in[9],  (const float*)d_in[13] };
    const float* gm[3] = { (const float*)d_in[6],  (const float*)d_in[10], (const float*)d_in[14] };
    const float* bt[3] = { (const float*)d_in[7],  (const float*)d_in[11], (const float*)d_in[15] };

    int n = in_sizes[0] / 128;    // 100000
    int E = in_sizes[1] / 2;      // 1000000
    float* out = (float*)d_out;

    int nb512 = (n + 511) / 512;

    // dtype sniff + degree/sort preprocessing
    k_detect<<<1, 256>>>((const unsigned long long*)ei);
    k_zero_hist<<<(n + 255) / 256, 256>>>(n);
    k_hist<<<(E + 255) / 256, 256>>>(ei, E);
    k_dinv<<<(n + 255) / 256, 256>>>(n);
    k_scan1<<<nb512, 512>>>(n);
    k_scan2<<<1, 256>>>(nb512);
    k_scan3<<<nb512, 512>>>(n);
    k_place<<<(E + 255) / 256, 256>>>(ei, E);

    // input projection: H = x @ proj_w + proj_b   (dst = g_H)
    k_gemm<<<(n + 63) / 64, 256>>>(x, proj_w, proj_b, /*dst_hw=*/0, n, 128);

    int agg_blocks = (n + 7) / 8;   // 8 warps per block
    for (int l = 0; l < 3; l++) {
        // HW = H @ w[l]   (src = g_H, dst = g_HW)
        k_gemm<<<(n + 63) / 64, 256>>>(nullptr, w[l], nullptr, /*dst_hw=*/1, n, 64);
        float* dst = (l < 2) ? nullptr : out;   // null -> g_H
        k_agg<<<agg_blocks, 256>>>(b[l], gm[l], bt[l], dst, n, (l < 2) ? 1 : 0);
    }
}